// round 17
// baseline (speedup 1.0000x reference)
#include <cuda_runtime.h>
#include <cuda_fp16.h>
#include <math.h>
#include <stdint.h>

#define NB 2
#define LQ 2048
#define LK 1024
#define DM 1024
#define NH 16
#define DH 64

// ---------------- scratch (static device allocations; no cudaMalloc) -------
__device__ __half g_xnh[NB*LQ*DM];      // rmsnorm(x), fp16
__device__ __half g_xch[NB*LK*DM];      // rmsnorm(x_cross), fp16
__device__ __half g_oh[NB*LQ*DM];       // attention output, fp16 (b,l,h,d)
__device__ __half g_wth[4*1024*1024];   // transposed weights fp16: qt | kvt | ot
__device__ __half g_qh2[NB*NH*LQ*DH];   // q prepped fp16, (b,h,l,d)
__device__ __half g_kh2[NB*NH*LK*DH];   // k prepped fp16, (b,h,lc,d)
__device__ __half g_vh [NB*NH*LK*DH];   // v fp16, (b,h,lc,d)

__device__ __forceinline__ uint32_t smem_u32(const void* p) {
    uint32_t a;
    asm("{ .reg .u64 t; cvta.to.shared.u64 t, %1; cvt.u32.u64 %0, t; }" : "=r"(a) : "l"(p));
    return a;
}
__device__ __forceinline__ void cp16(uint32_t dst, const void* src) {
    asm volatile("cp.async.cg.shared.global [%0], [%1], 16;" :: "r"(dst), "l"(src));
}
#define CP_COMMIT() asm volatile("cp.async.commit_group;" ::: "memory")

#define MMA_F16(c0,c1,c2,c3,a0,a1,a2,a3,b0,b1) \
    asm volatile("mma.sync.aligned.m16n8k16.row.col.f32.f16.f16.f32 " \
        "{%0,%1,%2,%3}, {%4,%5,%6,%7}, {%8,%9}, {%0,%1,%2,%3};" \
        : "+f"(c0), "+f"(c1), "+f"(c2), "+f"(c3) \
        : "r"(a0), "r"(a1), "r"(a2), "r"(a3), "r"(b0), "r"(b1))

#define LDSM_X4(r, addr) \
    asm volatile("ldmatrix.sync.aligned.m8n8.x4.shared.b16 {%0,%1,%2,%3}, [%4];" \
        : "=r"((r)[0]), "=r"((r)[1]), "=r"((r)[2]), "=r"((r)[3]) : "r"(addr))

#define LDSM_X4_T(r, addr) \
    asm volatile("ldmatrix.sync.aligned.m8n8.x4.trans.shared.b16 {%0,%1,%2,%3}, [%4];" \
        : "=r"((r)[0]), "=r"((r)[1]), "=r"((r)[2]), "=r"((r)[3]) : "r"(addr))

#define LDSM_X2_T(r0, r1, addr) \
    asm volatile("ldmatrix.sync.aligned.m8n8.x2.trans.shared.b16 {%0,%1}, [%2];" \
        : "=r"(r0), "=r"(r1) : "r"(addr))

__device__ __forceinline__ uint32_t packh2(float a, float b) {
    __half2 h = __floats2half2_rn(a, b);
    return *(uint32_t*)&h;
}
__device__ __forceinline__ float ex2(float x) {
    float r; asm("ex2.approx.f32 %0, %1;" : "=f"(r) : "f"(x)); return r;
}

// ---------------- fused prep: 3 weight transposes + 2 rmsnorms, one launch --
__global__ void prep_kernel(const float* __restrict__ x,
                            const float* __restrict__ xcr,
                            const float* __restrict__ nsc,
                            const float* __restrict__ ncs,
                            const float* __restrict__ q_w,
                            const float* __restrict__ kv_w,
                            const float* __restrict__ out_w) {
    __shared__ float tile[32][33];
    __shared__ float red[8];
    int blk = blockIdx.x;
    int t = threadIdx.x;
    if (blk < 4096) {
        int tx = t & 31, ty = t >> 5;
        const float* W; __half* Wt; int K, N, idx;
        if (blk < 1024)      { W = q_w;   Wt = g_wth;               K = 1024; N = 1024; idx = blk; }
        else if (blk < 3072) { W = kv_w;  Wt = g_wth + 1024*1024;   K = 1024; N = 2048; idx = blk - 1024; }
        else                 { W = out_w; Wt = g_wth + 3*1024*1024; K = 1024; N = 1024; idx = blk - 3072; }
        int nblk = N >> 5;
        int bn = (idx % nblk) << 5, bk = (idx / nblk) << 5;
        #pragma unroll
        for (int i = 0; i < 32; i += 8)
            tile[ty + i][tx] = W[(size_t)(bk + ty + i) * N + bn + tx];
        __syncthreads();
        #pragma unroll
        for (int i = 0; i < 32; i += 8)
            Wt[(size_t)(bn + ty + i) * K + bk + tx] = __float2half_rn(tile[tx][ty + i]);
    } else {
        int row = blk - 4096;
        const float* xr;
        const float* w;
        __half* yr;
        if (row < NB*LQ) {
            xr = x + (size_t)row * DM;   w = nsc;  yr = g_xnh + (size_t)row * DM;
        } else {
            int r2 = row - NB*LQ;
            xr = xcr + (size_t)r2 * DM;  w = ncs;  yr = g_xch + (size_t)r2 * DM;
        }
        float4 v = *(const float4*)(xr + t*4);
        float ss = v.x*v.x + v.y*v.y + v.z*v.z + v.w*v.w;
        #pragma unroll
        for (int o = 16; o > 0; o >>= 1) ss += __shfl_xor_sync(0xffffffffu, ss, o);
        if ((t & 31) == 0) red[t >> 5] = ss;
        __syncthreads();
        float tot = 0.f;
        #pragma unroll
        for (int i = 0; i < 8; i++) tot += red[i];
        float rs = rsqrtf(tot * (1.0f/DM) + 1e-6f);
        float4 wv = *(const float4*)(w + t*4);
        uint2 o2;
        o2.x = packh2(v.x * wv.x * rs, v.y * wv.y * rs);
        o2.y = packh2(v.z * wv.z * rs, v.w * wv.w * rs);
        *(uint2*)(yr + t*4) = o2;
    }
}

// ---------------- fp16 mma.sync GEMM: CTA 128x128, BK=64, 3 CTAs/SM --------
// 2-stage cp.async pipeline; bf loaded one x4 at a time (low reg pressure).
// mode 0: C = A@Bt^T + Cadd; mode 3: merged q (mode1) + kv (mode2) dispatch.
#define HG_STRIDE 72
#define HG_A_STG (128*HG_STRIDE)
#define HG_B_STG (128*HG_STRIDE)
#define HG_STG_TOT (HG_A_STG + HG_B_STG)
#define HG_SMEM (2 * HG_STG_TOT * 2)      // 73728 bytes, 2 stages
__global__ void __launch_bounds__(256, 3)
hgemm_kernel(const __half* __restrict__ A, const __half* __restrict__ Bt,
             const float* __restrict__ Cadd, float* __restrict__ C,
             int N, int mode,
             const float* __restrict__ pos,
             const float* __restrict__ scale,
             const float* __restrict__ freqs) {
    extern __shared__ __half smh[];
    const int K = 1024;
    uint32_t sbase = smem_u32(smh);
    int t = threadIdx.x;
    int wid = t >> 5, lane = t & 31;
    int g = lane >> 2, t4 = lane & 3;
    int lane16 = lane & 15;
    int lwoff = (lane >> 4) << 2;
    int wm = (wid >> 1) * 32;
    int wn = (wid & 1) * 64;

    int bm, bn;
    if (mode == 3) {
        int blk = blockIdx.x;
        if (blk < 256) {
            mode = 1; A = g_xnh; Bt = g_wth; N = 1024;
            bm = (blk >> 3) * 128; bn = (blk & 7) * 128;
        } else {
            mode = 2; blk -= 256; A = g_xch; Bt = g_wth + 1024*1024; N = 2048;
            bm = (blk >> 4) * 128; bn = (blk & 15) * 128;
        }
    } else {
        bm = blockIdx.y * 128; bn = blockIdx.x * 128;
    }

    const __half* Ab = A  + (size_t)bm * K;
    const __half* Bb = Bt + (size_t)bn * K;

    float c[2][8][4];
    #pragma unroll
    for (int mt = 0; mt < 2; mt++)
        #pragma unroll
        for (int nt = 0; nt < 8; nt++)
            #pragma unroll
            for (int i = 0; i < 4; i++) c[mt][nt][i] = 0.f;

    const int nch = K >> 6;

    auto prefetch = [&](int ch, int s) {
        const __half* a = Ab + ch * 64;
        const __half* b = Bb + ch * 64;
        uint32_t abase = sbase + (uint32_t)(s * HG_STG_TOT) * 2;
        uint32_t bbase = abase + (uint32_t)HG_A_STG * 2;
        #pragma unroll
        for (int i = 0; i < 4; i++) {
            int f = t + i*256;
            int row = f >> 3;
            int col8 = (f & 7) * 8;
            uint32_t off = (uint32_t)(row * HG_STRIDE + col8) * 2;
            cp16(abase + off, a + (size_t)row * K + col8);
            cp16(bbase + off, b + (size_t)row * K + col8);
        }
        CP_COMMIT();
    };

    prefetch(0, 0);
    prefetch(1, 1);

    for (int ch = 0; ch < nch; ch++) {
        int s = ch & 1;
        if (ch + 1 < nch) { asm volatile("cp.async.wait_group 1;" ::: "memory"); }
        else              { asm volatile("cp.async.wait_group 0;" ::: "memory"); }
        __syncthreads();
        uint32_t sA = sbase + (uint32_t)(s * HG_STG_TOT) * 2;
        uint32_t sB = sA + (uint32_t)HG_A_STG * 2;
        #pragma unroll
        for (int kk = 0; kk < 4; kk++) {
            int kw = kk * 8;
            uint32_t af[2][4];
            #pragma unroll
            for (int mt = 0; mt < 2; mt++)
                LDSM_X4(af[mt], sA + (uint32_t)((wm + mt*16 + lane16)*36 + kw + lwoff)*4);
            #pragma unroll
            for (int p = 0; p < 4; p++) {
                uint32_t bf[4];
                LDSM_X4(bf, sB + (uint32_t)((wn + p*16 + lane16)*36 + kw + lwoff)*4);
                #pragma unroll
                for (int sub = 0; sub < 2; sub++) {
                    int nt = p*2 + sub;
                    #pragma unroll
                    for (int mt = 0; mt < 2; mt++)
                        MMA_F16(c[mt][nt][0], c[mt][nt][1], c[mt][nt][2], c[mt][nt][3],
                                af[mt][0], af[mt][1], af[mt][2], af[mt][3],
                                bf[sub], bf[2 + sub]);
                }
            }
        }
        __syncthreads();
        if (ch + 2 < nch) prefetch(ch + 2, s);
    }

    if (mode == 0) {
        #pragma unroll
        for (int mt = 0; mt < 2; mt++) {
            int row = bm + wm + mt*16 + g;
            #pragma unroll
            for (int nt = 0; nt < 8; nt++) {
                int col = bn + wn + nt*8 + 2*t4;
                size_t i0 = (size_t)row * N + col;
                size_t i1 = (size_t)(row + 8) * N + col;
                float2 r0 = { c[mt][nt][0], c[mt][nt][1] };
                float2 r1 = { c[mt][nt][2], c[mt][nt][3] };
                float2 a0 = *(const float2*)(Cadd + i0);
                float2 a1 = *(const float2*)(Cadd + i1);
                r0.x += a0.x; r0.y += a0.y;
                r1.x += a1.x; r1.y += a1.y;
                *(float2*)(C + i0) = r0;
                *(float2*)(C + i1) = r1;
            }
        }
    } else if (mode == 1) {
        int h = (bn + wn) >> 6;
        float sqs = sqrtf(scale[h]);
        float fr[4][2];
        #pragma unroll
        for (int nt = 0; nt < 4; nt++)
            #pragma unroll
            for (int e = 0; e < 2; e++)
                fr[nt][e] = freqs[h*16 + ((nt*8 + 2*t4 + e) & 15)];
        #pragma unroll
        for (int mt = 0; mt < 2; mt++) {
            #pragma unroll
            for (int hr = 0; hr < 2; hr++) {
                int row = bm + wm + mt*16 + g + hr*8;
                int i = hr*2;
                float ss = 0.f;
                #pragma unroll
                for (int nt = 0; nt < 8; nt++)
                    ss += c[mt][nt][i]*c[mt][nt][i] + c[mt][nt][i+1]*c[mt][nt][i+1];
                ss += __shfl_xor_sync(0xffffffffu, ss, 1);
                ss += __shfl_xor_sync(0xffffffffu, ss, 2);
                float rn = sqs * rsqrtf(ss + 1e-6f);
                int b = row >> 11, l = row & (LQ - 1);
                float p0 = pos[row*2], p1 = pos[row*2 + 1];
                __half* outp = g_qh2 + ((size_t)(b*NH + h) * LQ + l) * DH;
                #pragma unroll
                for (int nt = 0; nt < 4; nt++) {
                    float olo[2], ohi[2];
                    #pragma unroll
                    for (int e = 0; e < 2; e++) {
                        float q1 = c[mt][nt][i+e] * rn;
                        float q2 = c[mt][nt+4][i+e] * rn;
                        float th = ((nt < 2) ? p0 : p1) * fr[nt][e];
                        float sn, cs;
                        __sincosf(th, &sn, &cs);
                        olo[e] = q1*cs - q2*sn;
                        ohi[e] = q2*cs + q1*sn;
                    }
                    *(uint32_t*)(outp + nt*8 + 2*t4)      = packh2(olo[0], olo[1]);
                    *(uint32_t*)(outp + nt*8 + 2*t4 + 32) = packh2(ohi[0], ohi[1]);
                }
            }
        }
    } else {
        int colb = bn + wn;
        int which = colb >> 10;
        int h = (colb & 1023) >> 6;
        float sqs = sqrtf(scale[h]);
        #pragma unroll
        for (int mt = 0; mt < 2; mt++) {
            #pragma unroll
            for (int hr = 0; hr < 2; hr++) {
                int row = bm + wm + mt*16 + g + hr*8;
                int i = hr*2;
                int b = row >> 10, lc = row & (LK - 1);
                if (which == 0) {
                    float ss = 0.f;
                    #pragma unroll
                    for (int nt = 0; nt < 8; nt++)
                        ss += c[mt][nt][i]*c[mt][nt][i] + c[mt][nt][i+1]*c[mt][nt][i+1];
                    ss += __shfl_xor_sync(0xffffffffu, ss, 1);
                    ss += __shfl_xor_sync(0xffffffffu, ss, 2);
                    float rn = sqs * rsqrtf(ss + 1e-6f);
                    __half* outp = g_kh2 + ((size_t)(b*NH + h) * LK + lc) * DH;
                    #pragma unroll
                    for (int nt = 0; nt < 8; nt++)
                        *(uint32_t*)(outp + nt*8 + 2*t4) =
                            packh2(c[mt][nt][i]*rn, c[mt][nt][i+1]*rn);
                } else {
                    __half* outp = g_vh + ((size_t)(b*NH + h) * LK + lc) * DH;
                    #pragma unroll
                    for (int nt = 0; nt < 8; nt++)
                        *(uint32_t*)(outp + nt*8 + 2*t4) =
                            packh2(c[mt][nt][i], c[mt][nt][i+1]);
                }
            }
        }
    }
}

// ---------------- Flash attention: static softmax, tensor-pipe row sums ----
#define FL_STRIDE 72
#define FL_SMEM ((128 + 4*64) * FL_STRIDE * 2)
__global__ void __launch_bounds__(128, 2)
flash_mma_kernel() {
    extern __shared__ __half smh[];
    uint32_t sq = smem_u32(smh);                        // Q [128][72]
    uint32_t skv[2][2];
    #pragma unroll
    for (int s2 = 0; s2 < 2; s2++)
        #pragma unroll
        for (int m2 = 0; m2 < 2; m2++)
            skv[s2][m2] = smem_u32(smh + (128 + (s2*2 + m2)*64) * FL_STRIDE);
    int t = threadIdx.x;
    int lane = t & 31;
    int g = lane >> 2, t4 = lane & 3;
    int lane16 = lane & 15;
    int lwoff = (lane >> 4) << 2;
    int wm = (t >> 5) * 32;
    int bh = blockIdx.y;
    int q0 = blockIdx.x * 128;
    const __half* qg = g_qh2 + ((size_t)bh * LQ + q0) * DH;
    const __half* kg = g_kh2 + (size_t)bh * LK * DH;
    const __half* vg = g_vh  + (size_t)bh * LK * DH;

    {
        #pragma unroll
        for (int i = 0; i < 8; i++) {
            int f = t + i*128;
            int r = f >> 3, c = (f & 7) * 8;
            cp16(sq + (uint32_t)(r*FL_STRIDE + c)*2, qg + (size_t)r*DH + c);
        }
        CP_COMMIT();
    }
    // init V-padding: col 64 = 1.0, cols 65-71 = 0
    {
        int s2 = t >> 6, row = t & 63;
        uint4 ones = { 0x00003C00u, 0u, 0u, 0u };
        __half* vbuf = smh + (128 + (s2*2 + 1)*64) * FL_STRIDE;
        *(uint4*)(vbuf + row*FL_STRIDE + 64) = ones;
    }
    auto prefetch = [&](int tile, int s) {
        const __half* ks = kg + (size_t)tile * 64 * DH;
        const __half* vs = vg + (size_t)tile * 64 * DH;
        #pragma unroll
        for (int i = 0; i < 4; i++) {
            int f = t + i*128;
            int r = f >> 3, c = (f & 7) * 8;
            cp16(skv[s][0] + (uint32_t)(r*FL_STRIDE + c)*2, ks + (size_t)r*DH + c);
            cp16(skv[s][1] + (uint32_t)(r*FL_STRIDE + c)*2, vs + (size_t)r*DH + c);
        }
        CP_COMMIT();
    };
    prefetch(0, 0);
    prefetch(1, 1);

    asm volatile("cp.async.wait_group 2;" ::: "memory");
    __syncthreads();

    uint32_t qf[2][4][4];
    #pragma unroll
    for (int mt = 0; mt < 2; mt++)
        #pragma unroll
        for (int kk = 0; kk < 4; kk++)
            LDSM_X4(qf[mt][kk], sq + (uint32_t)((wm + mt*16 + lane16)*36 + kk*8 + lwoff)*4);

    float acc[2][8][4];
    float accl[2][4];
    #pragma unroll
    for (int mt = 0; mt < 2; mt++) {
        #pragma unroll
        for (int nt = 0; nt < 8; nt++)
            #pragma unroll
            for (int i = 0; i < 4; i++) acc[mt][nt][i] = 0.f;
        #pragma unroll
        for (int i = 0; i < 4; i++) accl[mt][i] = 0.f;
    }

    const float LOG2E = 1.4426950408889634f;
    const float CSH = 12.0f - 10.0f * 1.4426950408889634f;

    const int NT = LK / 64;
    for (int tl = 0; tl < NT; tl++) {
        int s = tl & 1;
        if (tl + 1 < NT) { asm volatile("cp.async.wait_group 1;" ::: "memory"); }
        else             { asm volatile("cp.async.wait_group 0;" ::: "memory"); }
        __syncthreads();
        uint32_t sk = skv[s][0], sv = skv[s][1];

        float sc[2][8][4];
        #pragma unroll
        for (int mt = 0; mt < 2; mt++)
            #pragma unroll
            for (int nt = 0; nt < 8; nt++)
                #pragma unroll
                for (int i = 0; i < 4; i++) sc[mt][nt][i] = 0.f;
        #pragma unroll
        for (int kk = 0; kk < 4; kk++) {
            uint32_t bf[4][4];
            #pragma unroll
            for (int p = 0; p < 4; p++)
                LDSM_X4(bf[p], sk + (uint32_t)((p*16 + lane16)*36 + kk*8 + lwoff)*4);
            #pragma unroll
            for (int nt = 0; nt < 8; nt++) {
                uint32_t b0 = bf[nt >> 1][nt & 1];
                uint32_t b1 = bf[nt >> 1][2 + (nt & 1)];
                #pragma unroll
                for (int mt = 0; mt < 2; mt++)
                    MMA_F16(sc[mt][nt][0], sc[mt][nt][1], sc[mt][nt][2], sc[mt][nt][3],
                            qf[mt][kk][0], qf[mt][kk][1], qf[mt][kk][2], qf[mt][kk][3], b0, b1);
            }
        }

        #pragma unroll
        for (int mt = 0; mt < 2; mt++)
            #pragma unroll
            for (int nt = 0; nt < 8; nt++) {
                sc[mt][nt][0] = ex2(fmaf(sc[mt][nt][0], LOG2E, CSH));
                sc[mt][nt][1] = ex2(fmaf(sc[mt][nt][1], LOG2E, CSH));
                sc[mt][nt][2] = ex2(fmaf(sc[mt][nt][2], LOG2E, CSH));
                sc[mt][nt][3] = ex2(fmaf(sc[mt][nt][3], LOG2E, CSH));
            }

        #pragma unroll
        for (int kk = 0; kk < 4; kk++) {
            uint32_t bf[4][4];
            #pragma unroll
            for (int p = 0; p < 4; p++)
                LDSM_X4_T(bf[p], sv + (uint32_t)((kk*16 + lane16)*36 + p*8 + lwoff)*4);
            uint32_t bl0, bl1;
            LDSM_X2_T(bl0, bl1, sv + (uint32_t)((kk*16 + lane16)*36 + 32)*4);
            #pragma unroll
            for (int mt = 0; mt < 2; mt++) {
                uint32_t a0 = packh2(sc[mt][2*kk  ][0], sc[mt][2*kk  ][1]);
                uint32_t a1 = packh2(sc[mt][2*kk  ][2], sc[mt][2*kk  ][3]);
                uint32_t a2 = packh2(sc[mt][2*kk+1][0], sc[mt][2*kk+1][1]);
                uint32_t a3 = packh2(sc[mt][2*kk+1][2], sc[mt][2*kk+1][3]);
                #pragma unroll
                for (int nt = 0; nt < 8; nt++) {
                    uint32_t b0 = bf[nt >> 1][(nt & 1) * 2];
                    uint32_t b1 = bf[nt >> 1][(nt & 1) * 2 + 1];
                    MMA_F16(acc[mt][nt][0], acc[mt][nt][1], acc[mt][nt][2], acc[mt][nt][3],
                            a0, a1, a2, a3, b0, b1);
                }
                MMA_F16(accl[mt][0], accl[mt][1], accl[mt][2], accl[mt][3],
                        a0, a1, a2, a3, bl0, bl1);
            }
        }
        __syncthreads();
        if (tl + 2 < NT) prefetch(tl + 2, s);
    }

    int b = bh >> 4, h = bh & 15;
    __half* og = g_oh + (size_t)(b*LQ + q0) * DM + h*DH;
    int qbase = lane & 28;
    #pragma unroll
    for (int mt = 0; mt < 2; mt++) {
        float l0 = __shfl_sync(0xffffffffu, accl[mt][0], qbase);
        float l1 = __shfl_sync(0xffffffffu, accl[mt][2], qbase);
        float inv0 = 1.0f / l0, inv1 = 1.0f / l1;
        #pragma unroll
        for (int nt = 0; nt < 8; nt++) {
            int col = nt*8 + 2*t4;
            *(uint32_t*)(og + (size_t)(wm + mt*16 + g    )*DM + col) =
                packh2(acc[mt][nt][0]*inv0, acc[mt][nt][1]*inv0);
            *(uint32_t*)(og + (size_t)(wm + mt*16 + g + 8)*DM + col) =
                packh2(acc[mt][nt][2]*inv1, acc[mt][nt][3]*inv1);
        }
    }
}

// ---------------- launch ----------------------------------------------------
extern "C" void kernel_launch(void* const* d_in, const int* in_sizes, int n_in,
                              void* d_out, int out_size) {
    const float* x     = (const float*)d_in[0];
    const float* pos   = (const float*)d_in[1];
    const float* xcr   = (const float*)d_in[2];
    const float* nsc   = (const float*)d_in[3];
    const float* ncs   = (const float*)d_in[4];
    const float* q_w   = (const float*)d_in[5];
    const float* kv_w  = (const float*)d_in[6];
    const float* scl   = (const float*)d_in[7];
    const float* out_w = (const float*)d_in[8];
    const float* freqs = (const float*)d_in[9];
    float* out = (float*)d_out;

    __half *oh, *wth;
    cudaGetSymbolAddress((void**)&oh,  g_oh);
    cudaGetSymbolAddress((void**)&wth, g_wth);
    __half* ot = wth + 3*1024*1024;

    // 0+1. fused: weight transposes + RMS norms
    prep_kernel<<<4096 + NB*LQ + NB*LK, 256>>>(x, xcr, nsc, ncs, q_w, kv_w, out_w);

    // 2. merged q + kv projections (512 CTAs, mode-3 dispatch, fused epilogues)
    cudaFuncSetAttribute(hgemm_kernel, cudaFuncAttributeMaxDynamicSharedMemorySize, HG_SMEM);
    hgemm_kernel<<<512, 256, HG_SMEM>>>(
        nullptr, nullptr, nullptr, nullptr, 0, 3, pos, scl, freqs);

    // 3. attention (static softmax, tensor-pipe row sums)
    cudaFuncSetAttribute(flash_mma_kernel, cudaFuncAttributeMaxDynamicSharedMemorySize, FL_SMEM);
    flash_mma_kernel<<<dim3(LQ/128, NB*NH), 128, FL_SMEM>>>();

    // 4. output projection + residual
    hgemm_kernel<<<dim3(DM/128, NB*LQ/128), 256, HG_SMEM>>>(
        oh, ot, x, out, DM, 0, nullptr, nullptr, nullptr);
}